// round 4
// baseline (speedup 1.0000x reference)
#include <cuda_runtime.h>
#include <math.h>

#define EPSF 1e-6f
#define TPB 128

__device__ float g_part[8192];
__device__ unsigned int g_ticket;   // zero-init; self-resets each launch

__global__ __launch_bounds__(TPB)
void rotated_iou_loss_kernel(const float* __restrict__ pred,
                             const float* __restrict__ target,
                             const float* __restrict__ weight,
                             float* __restrict__ out,
                             int n, float inv_n)
{
    // [slot][tid] layout: bank = tid%32 for ANY slot -> conflict-free for
    // static stores AND per-lane dynamic gathers.
    __shared__ float sX[24][TPB];
    __shared__ float sY[24][TPB];

    int tid = threadIdx.x;
    int i = blockIdx.x * TPB + tid;
    float loss = 0.0f;

    if (i < n) {
        const float* pp = pred + i * 5;
        const float* tp = target + i * 5;
        float p_x = pp[0], p_y = pp[1], p_w = pp[2], p_h = pp[3], p_a = pp[4];
        float t_x = tp[0], t_y = tp[1], t_w = tp[2], t_h = tp[3], t_a = tp[4];

        float ps, pc, ts, tc;
        __sincosf(p_a, &ps, &pc);
        __sincosf(t_a, &ts, &tc);

        const float dxs[4] = { 0.5f, -0.5f, -0.5f,  0.5f };
        const float dys[4] = { 0.5f,  0.5f, -0.5f, -0.5f };
        float c1x[4], c1y[4], c2x[4], c2y[4];
        #pragma unroll
        for (int j = 0; j < 4; j++) {
            float lx = p_w * dxs[j], ly = p_h * dys[j];
            c1x[j] = p_x + lx * pc - ly * ps;
            c1y[j] = p_y + lx * ps + ly * pc;
            lx = t_w * dxs[j]; ly = t_h * dys[j];
            c2x[j] = t_x + lx * tc - ly * ts;
            c2y[j] = t_y + lx * ts + ly * tc;
        }

        // ---- Pass A: fixed-slot candidates -> smem (static indices) ----
        // slots 0..15 intersections (pred-edge-major), 16..19 c1, 20..23 c2.
        unsigned vmask = 0u;
        float sx = 0.0f, sy = 0.0f;

        #pragma unroll
        for (int j = 0; j < 4; j++) {
            float p1x = c1x[j], p1y = c1y[j];
            float d1x = c1x[(j + 1) & 3] - p1x;
            float d1y = c1y[(j + 1) & 3] - p1y;
            #pragma unroll
            for (int k = 0; k < 4; k++) {
                int s = j * 4 + k;
                float p2x = c2x[k], p2y = c2y[k];
                float d2x = c2x[(k + 1) & 3] - p2x;
                float d2y = c2y[(k + 1) & 3] - p2y;
                float den = d1x * d2y - d1y * d2x;
                float inv = __fdividef(1.0f, den);
                float rpx = p2x - p1x, rpy = p2y - p1y;
                float tt = (rpx * d2y - rpy * d2x) * inv;
                float uu = (rpx * d1y - rpy * d1x) * inv;
                bool ok = (fabsf(den) > 1e-8f) &&
                          (tt >= 0.0f) && (tt <= 1.0f) &&
                          (uu >= 0.0f) && (uu <= 1.0f);
                float ix = ok ? fmaf(tt, d1x, p1x) : 0.0f;
                float iy = ok ? fmaf(tt, d1y, p1y) : 0.0f;
                sX[s][tid] = ix; sY[s][tid] = iy;
                sx += ix; sy += iy;
                if (ok) vmask |= (1u << s);
            }
        }

        const float tol = 1e-6f;
        {   // pred corners inside target
            float hw = t_w * 0.5f + tol, hh = t_h * 0.5f + tol;
            #pragma unroll
            for (int j = 0; j < 4; j++) {
                float dx = c1x[j] - t_x, dy = c1y[j] - t_y;
                float u  =  dx * tc + dy * ts;
                float v  = -dx * ts + dy * tc;
                bool ok = (fabsf(u) <= hw) && (fabsf(v) <= hh);
                int s = 16 + j;
                float ix = ok ? c1x[j] : 0.0f;
                float iy = ok ? c1y[j] : 0.0f;
                sX[s][tid] = ix; sY[s][tid] = iy;
                sx += ix; sy += iy;
                if (ok) vmask |= (1u << s);
            }
        }
        {   // target corners inside pred
            float hw = p_w * 0.5f + tol, hh = p_h * 0.5f + tol;
            #pragma unroll
            for (int j = 0; j < 4; j++) {
                float dx = c2x[j] - p_x, dy = c2y[j] - p_y;
                float u  =  dx * pc + dy * ps;
                float v  = -dx * ps + dy * pc;
                bool ok = (fabsf(u) <= hw) && (fabsf(v) <= hh);
                int s = 20 + j;
                float ix = ok ? c2x[j] : 0.0f;
                float iy = ok ? c2y[j] : 0.0f;
                sX[s][tid] = ix; sY[s][tid] = iy;
                sx += ix; sy += iy;
                if (ok) vmask |= (1u << s);
            }
        }

        int m = __popc(vmask);
        float cnt = fmaxf((float)m, 1.0f);
        float invc = __fdividef(1.0f, cnt);
        float mx = sx * invc, my = sy * invc;

        // ---- Pass B: keys (registers only) ----
        // pseudo-angle, monotone in atan2; top 27 bits | 5-bit slot.
        unsigned keys[32];
        #pragma unroll
        for (int s = 0; s < 24; s++) {
            bool v = (vmask >> s) & 1u;
            float x = sX[s][tid] - mx;     // static LDS, conflict-free
            float y = sY[s][tid] - my;
            float d = fabsf(x) + fabsf(y);
            float r = __fdividef(x, d);
            float pa = (y >= 0.0f) ? (1.0f - r) : (r - 1.0f);
            pa = (d > 0.0f) ? pa : 0.0f;
            unsigned b = __float_as_uint(pa);
            unsigned okey = ((int)b < 0) ? ~b : (b | 0x80000000u);
            keys[s] = v ? ((okey & 0xFFFFFFE0u) | (unsigned)s)
                        : (0xFFFFFFE0u | (unsigned)s);
        }
        #pragma unroll
        for (int s = 24; s < 32; s++) keys[s] = 0xFFFFFFFFu;

        // Batcher odd-even mergesort, register-resident, fully uniform.
        #pragma unroll
        for (int p = 1; p < 32; p <<= 1) {
            #pragma unroll
            for (int k = p; k >= 1; k >>= 1) {
                #pragma unroll
                for (int j = (k & (p - 1)); j + k < 32; j += 2 * k) {
                    #pragma unroll
                    for (int q = 0; q < k; q++) {
                        if (q + j + k < 32 &&
                            (q + j) / (2 * p) == (q + j + k) / (2 * p)) {
                            unsigned a = keys[q + j], b = keys[q + j + k];
                            keys[q + j]     = min(a, b);
                            keys[q + j + k] = max(a, b);
                        }
                    }
                }
            }
        }

        // ---- Pass C: cyclic shoelace over sorted ranks ----
        // rank >= m -> exact zeros, reproducing the reference's masked-roll
        // semantics (wrap term auto-vanishes unless m == 24).
        float area2 = 0.0f;
        float fx, fy, prx, pry;
        {
            int idx = keys[0] & 31;
            bool v = 0 < m;
            fx = v ? sX[idx][tid] - mx : 0.0f;   // dynamic LDS, conflict-free
            fy = v ? sY[idx][tid] - my : 0.0f;
            prx = fx; pry = fy;
        }
        #pragma unroll
        for (int t = 1; t < 24; t++) {
            int idx = keys[t] & 31;
            bool v = t < m;
            float gx = v ? sX[idx][tid] - mx : 0.0f;
            float gy = v ? sY[idx][tid] - my : 0.0f;
            area2 += prx * gy - pry * gx;
            prx = gx; pry = gy;
        }
        area2 += prx * fy - pry * fx;

        float inter = 0.5f * fabsf(area2);
        float uni = p_w * p_h + t_w * t_h - inter;
        float iou = __fdividef(inter, fmaxf(uni, EPSF));
        iou = fmaxf(iou, EPSF);
        loss = (1.0f - iou * iou * iou) * weight[i];
    }

    // ---- block reduction -> per-block partial (deterministic) ----
    #pragma unroll
    for (int o = 16; o > 0; o >>= 1)
        loss += __shfl_down_sync(0xffffffffu, loss, o);

    __shared__ float warp_sums[4];
    __shared__ bool is_last;
    int lane = tid & 31;
    int wid  = tid >> 5;
    if (lane == 0) warp_sums[wid] = loss;
    __syncthreads();

    if (wid == 0) {
        float v = (lane < 4) ? warp_sums[lane] : 0.0f;
        v += __shfl_down_sync(0xffffffffu, v, 2);
        v += __shfl_down_sync(0xffffffffu, v, 1);
        if (lane == 0) {
            g_part[blockIdx.x] = v;
            __threadfence();
            unsigned int t = atomicAdd(&g_ticket, 1u);
            is_last = (t == gridDim.x - 1);
        }
    }
    __syncthreads();

    // ---- last block: fixed-order final reduction ----
    if (is_last) {
        int nb = gridDim.x;
        double s = 0.0;
        for (int b = tid; b < nb; b += TPB)
            s += (double)g_part[b];
        #pragma unroll
        for (int o = 16; o > 0; o >>= 1)
            s += __shfl_down_sync(0xffffffffu, s, o);
        __shared__ double dsum[4];
        if (lane == 0) dsum[wid] = s;
        __syncthreads();
        if (wid == 0) {
            double v = (lane < 4) ? dsum[lane] : 0.0;
            v += __shfl_down_sync(0xffffffffu, v, 2);
            v += __shfl_down_sync(0xffffffffu, v, 1);
            if (lane == 0) {
                out[0] = (float)(v * (double)inv_n);
                g_ticket = 0u;
            }
        }
    }
}

extern "C" void kernel_launch(void* const* d_in, const int* in_sizes, int n_in,
                              void* d_out, int out_size) {
    const float* pred   = (const float*)d_in[0];
    const float* target = (const float*)d_in[1];
    const float* wgt    = (const float*)d_in[2];
    float* out = (float*)d_out;

    int n = in_sizes[2];
    if (n * 5 != in_sizes[0]) n = in_sizes[0] / 5;

    int blocks = (n + TPB - 1) / TPB;   // 500k -> 3907 (< 8192)

    rotated_iou_loss_kernel<<<blocks, TPB>>>(pred, target, wgt, out,
                                             n, 1.0f / (float)n);
}

// round 5
// speedup vs baseline: 1.7444x; 1.7444x over previous
#include <cuda_runtime.h>
#include <math.h>

#define EPSF 1e-6f
#define TPB 256

__device__ float g_part[4096];
__device__ unsigned int g_ticket;   // zero-init; self-resets each launch

// Clip polygon (ix,iy,n) against half-plane sign*coord <= bound.
// AXIS 0 = x, 1 = y. Output CCW order preserved. Returns new count (<= n+1).
template<int AXIS>
__device__ __forceinline__ int clip_hp(const float* ix, const float* iy, int n,
                                       float sign, float bound,
                                       float* ox, float* oy)
{
    int m = 0;
    if (n == 0) return 0;
    float px = ix[n - 1], py = iy[n - 1];
    float dp = bound - sign * (AXIS == 0 ? px : py);
    for (int j = 0; j < n; j++) {
        float cx = ix[j], cy = iy[j];
        float dc = bound - sign * (AXIS == 0 ? cx : cy);
        bool cin = (dc >= 0.0f), pin = (dp >= 0.0f);
        if (cin != pin) {
            float t = __fdividef(dp, dp - dc);
            float nx = px + t * (cx - px);
            float ny = py + t * (cy - py);
            if (AXIS == 0) nx = sign * bound; else ny = sign * bound;
            ox[m] = nx; oy[m] = ny; m++;
        }
        if (cin) { ox[m] = cx; oy[m] = cy; m++; }
        px = cx; py = cy; dp = dc;
    }
    return m;
}

__global__ __launch_bounds__(TPB)
void rotated_iou_loss_kernel(const float* __restrict__ pred,
                             const float* __restrict__ target,
                             const float* __restrict__ weight,
                             float* __restrict__ out,
                             int n, float inv_n)
{
    int tid = threadIdx.x;
    int i = blockIdx.x * TPB + tid;
    float loss = 0.0f;

    if (i < n) {
        const float* pp = pred + i * 5;
        const float* tp = target + i * 5;
        float p_x = pp[0], p_y = pp[1], p_w = pp[2], p_h = pp[3], p_a = pp[4];
        float t_x = tp[0], t_y = tp[1], t_w = tp[2], t_h = tp[3], t_a = tp[4];

        // Target frame: rotate by -t_a, translate by -t_center.
        float tc, ts, cd, sd;
        __sincosf(t_a, &ts, &tc);
        __sincosf(p_a - t_a, &sd, &cd);

        float rx = p_x - t_x, ry = p_y - t_y;
        float cu =  rx * tc + ry * ts;       // pred center in target frame
        float cv = -rx * ts + ry * tc;

        // Pred corners (CCW, same ordering as reference) in target frame.
        const float dxs[4] = { 0.5f, -0.5f, -0.5f,  0.5f };
        const float dys[4] = { 0.5f,  0.5f, -0.5f, -0.5f };
        float A0x[8], A0y[8], A1x[8], A1y[8];
        #pragma unroll
        for (int j = 0; j < 4; j++) {
            float lx = p_w * dxs[j], ly = p_h * dys[j];
            A0x[j] = cu + lx * cd - ly * sd;
            A0y[j] = cv + lx * sd + ly * cd;
        }

        // Sutherland-Hodgman clip against |x| <= W/2, |y| <= H/2.
        float hw = t_w * 0.5f, hh = t_h * 0.5f;
        int m;
        m = clip_hp<0>(A0x, A0y, 4,  1.0f, hw, A1x, A1y);   //  x <=  hw
        m = clip_hp<0>(A1x, A1y, m, -1.0f, hw, A0x, A0y);   // -x <=  hw
        m = clip_hp<1>(A0x, A0y, m,  1.0f, hh, A1x, A1y);   //  y <=  hh
        m = clip_hp<1>(A1x, A1y, m, -1.0f, hh, A0x, A0y);   // -y <=  hh

        float inter = 0.0f;
        if (m >= 3) {
            // Centroid of vertex set (== reference's masked mean).
            float sx = 0.0f, sy = 0.0f;
            for (int j = 0; j < m; j++) { sx += A0x[j]; sy += A0y[j]; }
            float invc = __fdividef(1.0f, (float)m);
            float mx = sx * invc, my = sy * invc;

            // Cyclic shoelace (CCW clip order) + argmin/argmax of
            // original-frame pseudo-angle (monotone in atan2).
            float S = 0.0f;
            float prx = A0x[m - 1] - mx, pry = A0y[m - 1] - my;
            float minpa = 1e30f, maxpa = -1e30f;
            float qminx = 0.0f, qminy = 0.0f, qmaxx = 0.0f, qmaxy = 0.0f;
            for (int j = 0; j < m; j++) {
                float qx = A0x[j] - mx, qy = A0y[j] - my;
                S += prx * qy - pry * qx;
                prx = qx; pry = qy;
                // direction in ORIGINAL frame: rotate q by +t_a
                float ox = qx * tc - qy * ts;
                float oy = qx * ts + qy * tc;
                float d = fabsf(ox) + fabsf(oy);
                float r = __fdividef(ox, d);
                float pa = (oy >= 0.0f) ? (1.0f - r) : (r - 1.0f);
                if (pa < minpa) { minpa = pa; qminx = qx; qminy = qy; }
                if (pa > maxpa) { maxpa = pa; qmaxx = qx; qmaxy = qy; }
            }
            // reference sum = cyclic sum - closing term cross(p_last, p_first)
            float quirky = S - (qmaxx * qminy - qmaxy * qminx);
            inter = 0.5f * fabsf(quirky);
        }

        float uni = p_w * p_h + t_w * t_h - inter;
        float iou = __fdividef(inter, fmaxf(uni, EPSF));
        iou = fmaxf(iou, EPSF);
        loss = (1.0f - iou * iou * iou) * weight[i];
    }

    // ---- block reduction -> per-block partial (deterministic) ----
    #pragma unroll
    for (int o = 16; o > 0; o >>= 1)
        loss += __shfl_down_sync(0xffffffffu, loss, o);

    __shared__ float warp_sums[8];
    __shared__ bool is_last;
    int lane = tid & 31;
    int wid  = tid >> 5;
    if (lane == 0) warp_sums[wid] = loss;
    __syncthreads();

    if (wid == 0) {
        float v = (lane < 8) ? warp_sums[lane] : 0.0f;
        #pragma unroll
        for (int o = 4; o > 0; o >>= 1)
            v += __shfl_down_sync(0xffffffffu, v, o);
        if (lane == 0) {
            g_part[blockIdx.x] = v;
            __threadfence();
            unsigned int t = atomicAdd(&g_ticket, 1u);
            is_last = (t == gridDim.x - 1);
        }
    }
    __syncthreads();

    // ---- last block: fixed-order final reduction ----
    if (is_last) {
        int nb = gridDim.x;
        double s = 0.0;
        for (int b = tid; b < nb; b += TPB)
            s += (double)g_part[b];
        #pragma unroll
        for (int o = 16; o > 0; o >>= 1)
            s += __shfl_down_sync(0xffffffffu, s, o);
        __shared__ double dsum[8];
        if (lane == 0) dsum[wid] = s;
        __syncthreads();
        if (wid == 0) {
            double v = (lane < 8) ? dsum[lane] : 0.0;
            #pragma unroll
            for (int o = 4; o > 0; o >>= 1)
                v += __shfl_down_sync(0xffffffffu, v, o);
            if (lane == 0) {
                out[0] = (float)(v * (double)inv_n);
                g_ticket = 0u;
            }
        }
    }
}

extern "C" void kernel_launch(void* const* d_in, const int* in_sizes, int n_in,
                              void* d_out, int out_size) {
    const float* pred   = (const float*)d_in[0];
    const float* target = (const float*)d_in[1];
    const float* wgt    = (const float*)d_in[2];
    float* out = (float*)d_out;

    int n = in_sizes[2];
    if (n * 5 != in_sizes[0]) n = in_sizes[0] / 5;

    int blocks = (n + TPB - 1) / TPB;   // 500k -> 1954 (< 4096)

    rotated_iou_loss_kernel<<<blocks, TPB>>>(pred, target, wgt, out,
                                             n, 1.0f / (float)n);
}

// round 8
// speedup vs baseline: 2.8827x; 1.6525x over previous
#include <cuda_runtime.h>
#include <math.h>

#define EPSF 1e-6f
#define TPB 128

__device__ float g_part[8192];
__device__ unsigned int g_ticket;   // zero-init; self-resets each launch

__global__ __launch_bounds__(TPB)
void rotated_iou_loss_kernel(const float* __restrict__ pred,
                             const float* __restrict__ target,
                             const float* __restrict__ weight,
                             float* __restrict__ out,
                             int n, float inv_n)
{
    // Coalesced input staging.
    __shared__ float sP[5 * TPB];
    __shared__ float sT[5 * TPB];
    // Clip buffers, [slot][tid]: bank = tid%32 for any slot -> conflict-free
    // even with divergent per-lane slot indices.
    __shared__ float sBx[6][TPB], sBy[6][TPB];   // after x-slab (<=6 verts)
    __shared__ float sCx[8][TPB], sCy[8][TPB];   // after y-slab (<=8 verts)

    int tid = threadIdx.x;
    int i = blockIdx.x * TPB + tid;

    {   // stage inputs (coalesced)
        int base = blockIdx.x * TPB * 5;
        #pragma unroll
        for (int c = 0; c < 5; c++) {
            int k = tid + c * TPB;
            int g = base + k;
            bool ok = g < 5 * n;
            sP[k] = ok ? pred[g]   : 0.0f;
            sT[k] = ok ? target[g] : 0.0f;
        }
    }
    __syncthreads();

    float loss = 0.0f;

    if (i < n) {
        int r5 = tid * 5;   // stride-5 smem reads: gcd(5,32)=1 -> conflict-free
        float p_x = sP[r5+0], p_y = sP[r5+1], p_w = sP[r5+2], p_h = sP[r5+3], p_a = sP[r5+4];
        float t_x = sT[r5+0], t_y = sT[r5+1], t_w = sT[r5+2], t_h = sT[r5+3], t_a = sT[r5+4];

        float tc, ts, cd, sd;
        __sincosf(t_a, &ts, &tc);
        __sincosf(p_a - t_a, &sd, &cd);

        float rx = p_x - t_x, ry = p_y - t_y;
        float cu =  rx * tc + ry * ts;
        float cv = -rx * ts + ry * tc;

        // Pred quad (CCW) in target frame — stays in registers.
        const float dxs[4] = { 0.5f, -0.5f, -0.5f,  0.5f };
        const float dys[4] = { 0.5f,  0.5f, -0.5f, -0.5f };
        float qx[4], qy[4];
        #pragma unroll
        for (int j = 0; j < 4; j++) {
            float lx = p_w * dxs[j], ly = p_h * dys[j];
            qx[j] = cu + lx * cd - ly * sd;
            qy[j] = cv + lx * sd + ly * cd;
        }

        float hw = t_w * 0.5f, hh = t_h * 0.5f;

        // ---- Stage 1: clip against x-slab |x| <= hw (registers -> sB) ----
        int m1 = 0;
        #pragma unroll
        for (int j = 0; j < 4; j++) {
            float px = qx[j],          py = qy[j];
            float cx = qx[(j+1) & 3],  cy = qy[(j+1) & 3];
            bool pL = px < -hw, pH = px > hw;
            bool cL = cx < -hw, cH = cx > hw;
            float dx = cx - px, dy = cy - py;
            float inv = __fdividef(1.0f, dx);
            bool crossL = (pL != cL), crossH = (pH != cH);
            // emit crossings in order along the edge (by t)
            bool firstIsL = (dx > 0.0f);
            #pragma unroll
            for (int e = 0; e < 2; e++) {
                bool doL = (e == 0) ? firstIsL : !firstIsL;
                bool cross = doL ? crossL : crossH;
                if (cross) {
                    float bnd = doL ? -hw : hw;
                    float t = (bnd - px) * inv;
                    sBx[m1][tid] = bnd;
                    sBy[m1][tid] = py + t * dy;
                    m1++;
                }
            }
            if (!cL && !cH) { sBx[m1][tid] = cx; sBy[m1][tid] = cy; m1++; }
        }

        // ---- Stage 2: clip against y-slab |y| <= hh (sB -> sC) ----
        int m2 = 0;
        float sx = 0.0f, sy = 0.0f;
        if (m1 > 0) {
            float px = sBx[m1-1][tid], py = sBy[m1-1][tid];
            bool pL = py < -hh, pH = py > hh;
            for (int j = 0; j < m1; j++) {
                float cx = sBx[j][tid], cy = sBy[j][tid];
                bool cL = cy < -hh, cH = cy > hh;
                float dx = cx - px, dy = cy - py;
                float inv = __fdividef(1.0f, dy);
                bool crossL = (pL != cL), crossH = (pH != cH);
                bool firstIsL = (dy > 0.0f);
                #pragma unroll
                for (int e = 0; e < 2; e++) {
                    bool doL = (e == 0) ? firstIsL : !firstIsL;
                    bool cross = doL ? crossL : crossH;
                    if (cross) {
                        float bnd = doL ? -hh : hh;
                        float t = (bnd - py) * inv;
                        float nx = px + t * dx;
                        sCx[m2][tid] = nx; sCy[m2][tid] = bnd;
                        sx += nx; sy += bnd; m2++;
                    }
                }
                if (!cL && !cH) {
                    sCx[m2][tid] = cx; sCy[m2][tid] = cy;
                    sx += cx; sy += cy; m2++;
                }
                px = cx; py = cy; pL = cL; pH = cH;
            }
        }

        // ---- Area with the reference's quirky open-chain semantics ----
        float inter = 0.0f;
        if (m2 >= 3) {
            float invc = __fdividef(1.0f, (float)m2);
            float mx = sx * invc, my = sy * invc;

            float S = 0.0f;
            float prx = sCx[m2-1][tid] - mx, pry = sCy[m2-1][tid] - my;
            float minpa = 1e30f, maxpa = -1e30f;
            float qminx = 0.0f, qminy = 0.0f, qmaxx = 0.0f, qmaxy = 0.0f;
            for (int j = 0; j < m2; j++) {
                float vx = sCx[j][tid] - mx, vy = sCy[j][tid] - my;
                S += prx * vy - pry * vx;
                prx = vx; pry = vy;
                // pseudo-angle in ORIGINAL frame (monotone in atan2)
                float ox = vx * tc - vy * ts;
                float oy = vx * ts + vy * tc;
                float d = fabsf(ox) + fabsf(oy);
                float r = __fdividef(ox, d);
                float pa = (oy >= 0.0f) ? (1.0f - r) : (r - 1.0f);
                if (pa < minpa) { minpa = pa; qminx = vx; qminy = vy; }
                if (pa > maxpa) { maxpa = pa; qmaxx = vx; qmaxy = vy; }
            }
            float quirky = S - (qmaxx * qminy - qmaxy * qminx);
            inter = 0.5f * fabsf(quirky);
        }

        float uni = p_w * p_h + t_w * t_h - inter;
        float iou = __fdividef(inter, fmaxf(uni, EPSF));
        iou = fmaxf(iou, EPSF);
        loss = (1.0f - iou * iou * iou) * weight[i];
    }

    // ---- block reduction -> per-block partial (deterministic) ----
    #pragma unroll
    for (int o = 16; o > 0; o >>= 1)
        loss += __shfl_down_sync(0xffffffffu, loss, o);

    __shared__ float warp_sums[4];
    __shared__ int is_last;
    int lane = tid & 31;
    int wid  = tid >> 5;
    if (lane == 0) warp_sums[wid] = loss;
    __syncthreads();

    if (wid == 0) {
        float v = (lane < 4) ? warp_sums[lane] : 0.0f;
        v += __shfl_down_sync(0xffffffffu, v, 2);
        v += __shfl_down_sync(0xffffffffu, v, 1);
        if (lane == 0) {
            g_part[blockIdx.x] = v;
            __threadfence();
            unsigned int t = atomicAdd(&g_ticket, 1u);
            is_last = (t == gridDim.x - 1) ? 1 : 0;
        }
    }
    __syncthreads();

    // ---- last block: fixed-order final reduction ----
    if (is_last) {
        int nb = gridDim.x;
        double s = 0.0;
        for (int b = tid; b < nb; b += TPB)
            s += (double)g_part[b];
        #pragma unroll
        for (int o = 16; o > 0; o >>= 1)
            s += __shfl_down_sync(0xffffffffu, s, o);
        __shared__ double dsum[4];
        if (lane == 0) dsum[wid] = s;
        __syncthreads();
        if (wid == 0) {
            double v = (lane < 4) ? dsum[lane] : 0.0;
            v += __shfl_down_sync(0xffffffffu, v, 2);
            v += __shfl_down_sync(0xffffffffu, v, 1);
            if (lane == 0) {
                out[0] = (float)(v * (double)inv_n);
                g_ticket = 0u;
            }
        }
    }
}

extern "C" void kernel_launch(void* const* d_in, const int* in_sizes, int n_in,
                              void* d_out, int out_size) {
    const float* pred   = (const float*)d_in[0];
    const float* target = (const float*)d_in[1];
    const float* wgt    = (const float*)d_in[2];
    float* out = (float*)d_out;

    int n = in_sizes[2];
    if (n * 5 != in_sizes[0]) n = in_sizes[0] / 5;

    int blocks = (n + TPB - 1) / TPB;   // 500k -> 3907 (< 8192)

    rotated_iou_loss_kernel<<<blocks, TPB>>>(pred, target, wgt, out,
                                             n, 1.0f / (float)n);
}

// round 9
// speedup vs baseline: 3.0605x; 1.0617x over previous
#include <cuda_runtime.h>
#include <math.h>

#define EPSF 1e-6f
#define TPB 128

__device__ float g_part[8192];
__device__ unsigned int g_ticket;   // zero-init; self-resets each launch

__global__ __launch_bounds__(TPB)
void rotated_iou_loss_kernel(const float* __restrict__ pred,
                             const float* __restrict__ target,
                             const float* __restrict__ weight,
                             float* __restrict__ out,
                             int n, float inv_n)
{
    // One pool, two lives:
    //   life 1: input staging, 10*TPB floats (5 KB)
    //   life 2: clip buffers as float2 [slot][tid] (6 + 8 slots, 14 KB)
    // float2 at [slot][tid]: consecutive lanes -> consecutive 8B -> LDS.64/
    // STS.64 conflict-free, and still conflict-free under divergent slot idx.
    __shared__ __align__(16) char pool[14 * TPB * sizeof(float2)];
    float* sIn = (float*)pool;

    int tid = threadIdx.x;
    int i = blockIdx.x * TPB + tid;

    {   // coalesced staging
        int base = blockIdx.x * TPB * 5;
        int n5 = 5 * n;
        #pragma unroll
        for (int c = 0; c < 5; c++) {
            int k = tid + c * TPB;
            int g = base + k;
            bool ok = g < n5;
            sIn[k]           = ok ? pred[g]   : 0.0f;
            sIn[5 * TPB + k] = ok ? target[g] : 0.0f;
        }
    }
    __syncthreads();

    // Pull my 10 params into registers (stride-5: gcd(5,32)=1, conflict-free).
    int r5 = tid * 5;
    float p_x = sIn[r5+0], p_y = sIn[r5+1], p_w = sIn[r5+2],
          p_h = sIn[r5+3], p_a = sIn[r5+4];
    float t_x = sIn[5*TPB+r5+0], t_y = sIn[5*TPB+r5+1], t_w = sIn[5*TPB+r5+2],
          t_h = sIn[5*TPB+r5+3], t_a = sIn[5*TPB+r5+4];
    __syncthreads();   // staging dead -> pool becomes clip buffers

    float2* pB = (float2*)pool + tid;              // x-slab output, <=6 slots
    float2* pC = (float2*)pool + 6 * TPB + tid;    // y-slab output, <=8 slots

    float loss = 0.0f;
    if (i < n) {
        float tc, ts, cd, sd;
        __sincosf(t_a, &ts, &tc);
        __sincosf(p_a - t_a, &sd, &cd);

        float rx = p_x - t_x, ry = p_y - t_y;
        float cu =  rx * tc + ry * ts;
        float cv = -rx * ts + ry * tc;

        // Pred quad (CCW, reference corner order) in target frame — registers.
        const float dxs[4] = { 0.5f, -0.5f, -0.5f,  0.5f };
        const float dys[4] = { 0.5f,  0.5f, -0.5f, -0.5f };
        float qx[4], qy[4];
        #pragma unroll
        for (int j = 0; j < 4; j++) {
            float lx = p_w * dxs[j], ly = p_h * dys[j];
            qx[j] = cu + lx * cd - ly * sd;
            qy[j] = cv + lx * sd + ly * cd;
        }

        float hw = t_w * 0.5f, hh = t_h * 0.5f;

        // ---- Stage 1: x-slab |x| <= hw (registers -> pB) ----
        float2* curB = pB;
        #pragma unroll
        for (int j = 0; j < 4; j++) {
            float px = qx[j],         py = qy[j];
            float cx = qx[(j+1) & 3], cy = qy[(j+1) & 3];
            bool pL = px < -hw, pH = px > hw;
            bool cL = cx < -hw, cH = cx > hw;
            float dx = cx - px, dy = cy - py;
            float inv = __fdividef(1.0f, dx);
            bool crossL = (pL != cL), crossH = (pH != cH);
            bool firstIsL = dx > 0.0f;   // crossing order along the edge
            #pragma unroll
            for (int e = 0; e < 2; e++) {
                bool doL = (e == 0) ? firstIsL : !firstIsL;
                bool cr  = doL ? crossL : crossH;
                if (cr) {
                    float bnd = doL ? -hw : hw;
                    float t = (bnd - px) * inv;
                    *curB = make_float2(bnd, fmaf(t, dy, py));
                    curB += TPB;
                }
            }
            if (!cL && !cH) { *curB = make_float2(cx, cy); curB += TPB; }
        }
        int m1 = (int)((curB - pB) >> 7);   // /TPB

        // ---- Stage 2: y-slab |y| <= hh (pB -> pC) ----
        float sx = 0.0f, sy = 0.0f;
        float2* curC = pC;
        if (m1 > 0) {
            float2 prev = *(curB - TPB);
            float px = prev.x, py = prev.y;
            bool pLo = py < -hh, pHi = py > hh;
            float2* rB = pB;
            for (int j = 0; j < m1; j++, rB += TPB) {
                float2 cur = *rB;
                float cx = cur.x, cy = cur.y;
                bool cLo = cy < -hh, cHi = cy > hh;
                float dx = cx - px, dy = cy - py;
                float inv = __fdividef(1.0f, dy);
                bool crossL = (pLo != cLo), crossH = (pHi != cHi);
                bool firstIsL = dy > 0.0f;
                #pragma unroll
                for (int e = 0; e < 2; e++) {
                    bool doL = (e == 0) ? firstIsL : !firstIsL;
                    bool cr  = doL ? crossL : crossH;
                    if (cr) {
                        float bnd = doL ? -hh : hh;
                        float t = (bnd - py) * inv;
                        float nx = fmaf(t, dx, px);
                        *curC = make_float2(nx, bnd);
                        sx += nx; sy += bnd;
                        curC += TPB;
                    }
                }
                if (!cLo && !cHi) {
                    *curC = make_float2(cx, cy);
                    sx += cx; sy += cy;
                    curC += TPB;
                }
                px = cx; py = cy; pLo = cLo; pHi = cHi;
            }
        }
        int m2 = (int)((curC - pC) >> 7);

        // ---- Area with the reference's quirky open-chain semantics ----
        float inter = 0.0f;
        if (m2 >= 3) {
            float invc = __fdividef(1.0f, (float)m2);
            float mx = sx * invc, my = sy * invc;

            float2 last = *(curC - TPB);
            float prx = last.x - mx, pry = last.y - my;
            float S = 0.0f;
            float minpa = 1e30f, maxpa = -1e30f;
            float qminx = 0.0f, qminy = 0.0f, qmaxx = 0.0f, qmaxy = 0.0f;
            float2* rC = pC;
            for (int j = 0; j < m2; j++, rC += TPB) {
                float2 v = *rC;
                float vx = v.x - mx, vy = v.y - my;
                S += prx * vy - pry * vx;
                prx = vx; pry = vy;
                // pseudo-angle in ORIGINAL frame (monotone in atan2)
                float ox = vx * tc - vy * ts;
                float oy = vx * ts + vy * tc;
                float d = fabsf(ox) + fabsf(oy);
                float r = __fdividef(ox, d);
                float pa = (oy >= 0.0f) ? (1.0f - r) : (r - 1.0f);
                if (pa < minpa) { minpa = pa; qminx = vx; qminy = vy; }
                if (pa > maxpa) { maxpa = pa; qmaxx = vx; qmaxy = vy; }
            }
            // reference sum = cyclic sum - cross(p_last_sorted, p_first_sorted)
            float quirky = S - (qmaxx * qminy - qmaxy * qminx);
            inter = 0.5f * fabsf(quirky);
        }

        float uni = p_w * p_h + t_w * t_h - inter;
        float iou = __fdividef(inter, fmaxf(uni, EPSF));
        iou = fmaxf(iou, EPSF);
        loss = (1.0f - iou * iou * iou) * weight[i];
    }

    // ---- block reduction -> per-block partial (deterministic) ----
    #pragma unroll
    for (int o = 16; o > 0; o >>= 1)
        loss += __shfl_down_sync(0xffffffffu, loss, o);

    __shared__ float warp_sums[4];
    __shared__ int is_last;
    int lane = tid & 31;
    int wid  = tid >> 5;
    if (lane == 0) warp_sums[wid] = loss;
    __syncthreads();

    if (wid == 0) {
        float v = (lane < 4) ? warp_sums[lane] : 0.0f;
        v += __shfl_down_sync(0xffffffffu, v, 2);
        v += __shfl_down_sync(0xffffffffu, v, 1);
        if (lane == 0) {
            g_part[blockIdx.x] = v;
            __threadfence();
            unsigned int t = atomicAdd(&g_ticket, 1u);
            is_last = (t == gridDim.x - 1) ? 1 : 0;
        }
    }
    __syncthreads();

    // ---- last block: fixed-order final reduction ----
    if (is_last) {
        int nb = gridDim.x;
        double s = 0.0;
        for (int b = tid; b < nb; b += TPB)
            s += (double)g_part[b];
        #pragma unroll
        for (int o = 16; o > 0; o >>= 1)
            s += __shfl_down_sync(0xffffffffu, s, o);
        __shared__ double dsum[4];
        if (lane == 0) dsum[wid] = s;
        __syncthreads();
        if (wid == 0) {
            double v = (lane < 4) ? dsum[lane] : 0.0;
            v += __shfl_down_sync(0xffffffffu, v, 2);
            v += __shfl_down_sync(0xffffffffu, v, 1);
            if (lane == 0) {
                out[0] = (float)(v * (double)inv_n);
                g_ticket = 0u;
            }
        }
    }
}

extern "C" void kernel_launch(void* const* d_in, const int* in_sizes, int n_in,
                              void* d_out, int out_size) {
    const float* pred   = (const float*)d_in[0];
    const float* target = (const float*)d_in[1];
    const float* wgt    = (const float*)d_in[2];
    float* out = (float*)d_out;

    int n = in_sizes[2];
    if (n * 5 != in_sizes[0]) n = in_sizes[0] / 5;

    int blocks = (n + TPB - 1) / TPB;   // 500k -> 3907 (< 8192)

    rotated_iou_loss_kernel<<<blocks, TPB>>>(pred, target, wgt, out,
                                             n, 1.0f / (float)n);
}